// round 5
// baseline (speedup 1.0000x reference)
#include <cuda_runtime.h>

// Capsule routing (B=64, I=O=1024, 3 routing iters), restructured:
//   round0: s1 = (u@w)/O           -> g_s0
//   round1: V1 = squash(s1+bias)*LOG2E (inline);  s2 = sum_i t*softmax_o(t*V1) -> g_s1
//   round2: V = (squash(s1+b)+squash(s2+b))*LOG2E (inline); same sweep -> g_s2
//   final : out = squash(g_s2+bias); rezero g_s0/1/2
// Softmax sweep: warp PAIR owns one b; each warp 512 o (16 o/lane, registers).
// Packed f32x2 math; exp = MUFU ex2 (12/16) + scalar FFMA-imm poly (4/16).
// Per-ii denominator: shfl butterfly + smem exchange + named barrier (per pair).

#define BB 64
#define II 1024
#define OO 1024
#define ICHUNK 32
#define NCHUNK (II / ICHUNK)   // 32
#define LOG2E 1.4426950408889634f

typedef unsigned long long u64;

__device__ float g_s0[BB * OO];
__device__ float g_s1[BB * OO];
__device__ float g_s2[BB * OO];

__device__ __forceinline__ float ex2a(float x) {
    float r; asm("ex2.approx.f32 %0, %1;" : "=f"(r) : "f"(x)); return r;
}
__device__ __forceinline__ float rcpa(float x) {
    float r; asm("rcp.approx.f32 %0, %1;" : "=f"(r) : "f"(x)); return r;
}
__device__ __forceinline__ float warp_sum(float x) {
#pragma unroll
    for (int s = 16; s > 0; s >>= 1)
        x += __shfl_xor_sync(0xffffffffu, x, s);
    return x;
}
__device__ __forceinline__ u64 pk(float x, float y) {
    u64 r; asm("mov.b64 %0, {%1, %2};" : "=l"(r) : "f"(x), "f"(y)); return r;
}
__device__ __forceinline__ void upk(float& x, float& y, u64 v) {
    asm("mov.b64 {%0, %1}, %2;" : "=f"(x), "=f"(y) : "l"(v));
}
__device__ __forceinline__ u64 mul2(u64 a, u64 b) {
    u64 r; asm("mul.rn.f32x2 %0, %1, %2;" : "=l"(r) : "l"(a), "l"(b)); return r;
}
__device__ __forceinline__ u64 add2(u64 a, u64 b) {
    u64 r; asm("add.rn.f32x2 %0, %1, %2;" : "=l"(r) : "l"(a), "l"(b)); return r;
}
__device__ __forceinline__ u64 fma2(u64 a, u64 b, u64 c) {
    u64 r; asm("fma.rn.f32x2 %0, %1, %2, %3;" : "=l"(r) : "l"(a), "l"(b), "l"(c)); return r;
}
// scalar exp2, deg-4 Taylor; immediates compile to FFMA-imm (rt 1)
__device__ __forceinline__ float exp2s(float x) {
    float r = fmaf(x, 0.00961813f, 0.05550411f);
    r = fmaf(r, x, 0.24022651f);
    r = fmaf(r, x, 0.69314718f);
    return fmaf(r, x, 1.0f);
}
__device__ __forceinline__ float squash_f(float n2) {  // factor s.t. v = x*f
    const float n = sqrtf(n2);
    return n2 / ((1.0f + n2) * (n + 1e-5f));
}

// ---------------- softmax routing sweep (rounds 1 and 2) ----------------
// block: 8 warps = 4 pairs = 4 b; grid (NCHUNK, BB/4)
template <int ROUND>
__global__ void __launch_bounds__(256, 2)
softmax_kernel(const float* __restrict__ u, const float* __restrict__ w,
               const float* __restrict__ bias) {
    __shared__ float eslot[4][2][2];  // [pair][half][parity] partial-sum exchange

    const int wid   = threadIdx.x >> 5;
    const int lane  = threadIdx.x & 31;
    const int pair  = wid >> 1;
    const int half  = wid & 1;
    const int barid = pair + 1;
    const int chunk = blockIdx.x;
    const int b     = blockIdx.y * 4 + pair;
    const int i0    = chunk * ICHUNK;

    // ---- prologue: build V (squash of previous round(s), scaled by LOG2E) ----
    u64 V[8];
    {
        const float4* s0 = reinterpret_cast<const float4*>(&g_s0[b * OO]);
        const float4* bi = reinterpret_cast<const float4*>(bias);
        float4 x4[4], y4[4];
        float ssx = 0.0f, ssy = 0.0f;
#pragma unroll
        for (int k = 0; k < 4; k++) {
            const int idx = half * 128 + k * 32 + lane;
            float4 xv = s0[idx], bv = bi[idx];
            xv.x += bv.x; xv.y += bv.y; xv.z += bv.z; xv.w += bv.w;
            x4[k] = xv;
            ssx += xv.x * xv.x + xv.y * xv.y + xv.z * xv.z + xv.w * xv.w;
        }
        if (ROUND == 2) {
            const float4* s1 = reinterpret_cast<const float4*>(&g_s1[b * OO]);
#pragma unroll
            for (int k = 0; k < 4; k++) {
                const int idx = half * 128 + k * 32 + lane;
                float4 yv = s1[idx], bv = bi[idx];
                yv.x += bv.x; yv.y += bv.y; yv.z += bv.z; yv.w += bv.w;
                y4[k] = yv;
                ssy += yv.x * yv.x + yv.y * yv.y + yv.z * yv.z + yv.w * yv.w;
            }
        }
        ssx = warp_sum(ssx);
        if (ROUND == 2) ssy = warp_sum(ssy);
        // exchange half-norms with partner warp via eslot
        if (lane == 0) {
            eslot[pair][half][0] = ssx;
            if (ROUND == 2) eslot[pair][half][1] = ssy;
        }
        asm volatile("bar.sync %0, 64;" :: "r"(barid) : "memory");
        const float n2x = ssx + eslot[pair][half ^ 1][0];
        const float f1 = squash_f(n2x) * LOG2E;
        float f2 = 0.0f;
        if (ROUND == 2) {
            const float n2y = ssy + eslot[pair][half ^ 1][1];
            f2 = squash_f(n2y) * LOG2E;
        }
        asm volatile("bar.sync %0, 64;" :: "r"(barid) : "memory");  // eslot reusable
#pragma unroll
        for (int k = 0; k < 4; k++) {
            float v0 = x4[k].x * f1, v1 = x4[k].y * f1;
            float v2 = x4[k].z * f1, v3 = x4[k].w * f1;
            if (ROUND == 2) {
                v0 += y4[k].x * f2; v1 += y4[k].y * f2;
                v2 += y4[k].z * f2; v3 += y4[k].w * f2;
            }
            V[2 * k + 0] = pk(v0, v1);
            V[2 * k + 1] = pk(v2, v3);
        }
    }

    u64 acc[8];
#pragma unroll
    for (int m = 0; m < 8; m++) acc[m] = 0ull;

    const float au = u[b * II + i0 + lane];

#pragma unroll 1
    for (int ii = 0; ii < ICHUNK; ii++) {
        const float a = __shfl_sync(0xffffffffu, au, ii);
        const u64 a2 = pk(a, a);
        const float4* wrow = reinterpret_cast<const float4*>(w + (size_t)(i0 + ii) * OO)
                             + half * 128;
        u64 p[8];
        u64 esum2 = 0ull;
#pragma unroll
        for (int k = 0; k < 4; k++) {
            float4 wv = wrow[k * 32 + lane];
            u64 t01 = mul2(a2, pk(wv.x, wv.y));
            u64 t23 = mul2(a2, pk(wv.z, wv.w));
            u64 l01 = mul2(t01, V[2 * k + 0]);
            u64 l23 = mul2(t23, V[2 * k + 1]);
            float x0, x1, y0, y1;
            upk(x0, x1, l01); upk(y0, y1, l23);
            u64 e01, e23;
            if (k < 3) {   // MUFU path: 12 of 16 elems
                e01 = pk(ex2a(x0), ex2a(x1));
                e23 = pk(ex2a(y0), ex2a(y1));
            } else {       // FMA-pipe poly: 4 of 16
                e01 = pk(exp2s(x0), exp2s(x1));
                e23 = pk(exp2s(y0), exp2s(y1));
            }
            esum2 = add2(esum2, add2(e01, e23));
            p[2 * k + 0] = mul2(t01, e01);
            p[2 * k + 1] = mul2(t23, e23);
        }
        float e0, e1;
        upk(e0, e1, esum2);
        float es = warp_sum(e0 + e1);            // this warp's 512-o partial
        if (lane == 0) eslot[pair][half][ii & 1] = es;
        asm volatile("bar.sync %0, 64;" :: "r"(barid) : "memory");
        const float Z  = es + eslot[pair][half ^ 1][ii & 1];
        const float rZ = rcpa(Z);
        const u64 rZ2 = pk(rZ, rZ);
#pragma unroll
        for (int m = 0; m < 8; m++)
            acc[m] = fma2(p[m], rZ2, acc[m]);
    }

    float* gs = (ROUND == 1) ? &g_s1[b * OO] : &g_s2[b * OO];
#pragma unroll
    for (int k = 0; k < 4; k++) {
        float f0, f1v, f2v, f3;
        upk(f0, f1v, acc[2 * k + 0]);
        upk(f2v, f3, acc[2 * k + 1]);
        const int o = half * 512 + 128 * k + 4 * lane;
        atomicAdd(&gs[o + 0], f0);
        atomicAdd(&gs[o + 1], f1v);
        atomicAdd(&gs[o + 2], f2v);
        atomicAdd(&gs[o + 3], f3);
    }
}

// ---------------- round-0 GEMV: g_s0 = (u @ w)/O ----------------
__global__ void __launch_bounds__(256, 2)
gemv_kernel(const float* __restrict__ u, const float* __restrict__ w) {
    const int warp  = threadIdx.x >> 5;
    const int lane  = threadIdx.x & 31;
    const int chunk = blockIdx.x;   // 0..15 (64 i)
    const int og    = blockIdx.y;   // 0..7
    const int i0    = chunk * 64;
    const int ocol  = og * 128 + 4 * lane;

    u64 acc[16];
#pragma unroll
    for (int m = 0; m < 16; m++) acc[m] = 0ull;

#pragma unroll 1
    for (int hf = 0; hf < 2; hf++) {
        const int ih = i0 + hf * 32;
        float au[8];
#pragma unroll
        for (int j = 0; j < 8; j++)
            au[j] = u[(size_t)(warp * 8 + j) * II + ih + lane];
#pragma unroll 1
        for (int ii = 0; ii < 32; ii++) {
            const float4 wv = *reinterpret_cast<const float4*>(
                w + (size_t)(ih + ii) * OO + ocol);
            const u64 w01 = pk(wv.x, wv.y);
            const u64 w23 = pk(wv.z, wv.w);
#pragma unroll
            for (int j = 0; j < 8; j++) {
                const float a = __shfl_sync(0xffffffffu, au[j], ii);
                const u64 a2 = pk(a, a);
                acc[2 * j + 0] = fma2(a2, w01, acc[2 * j + 0]);
                acc[2 * j + 1] = fma2(a2, w23, acc[2 * j + 1]);
            }
        }
    }

    const u64 inv = pk(1.0f / OO, 1.0f / OO);
#pragma unroll
    for (int j = 0; j < 8; j++) {
        float f0, f1, f2, f3;
        upk(f0, f1, mul2(acc[2 * j + 0], inv));
        upk(f2, f3, mul2(acc[2 * j + 1], inv));
        float* gs = &g_s0[(size_t)(warp * 8 + j) * OO + ocol];
        atomicAdd(&gs[0], f0);
        atomicAdd(&gs[1], f1);
        atomicAdd(&gs[2], f2);
        atomicAdd(&gs[3], f3);
    }
}

// -------- final: out = squash(g_s2 + bias); rezero g_s0/1/2 --------
__global__ void __launch_bounds__(1024, 1)
final_kernel(const float* __restrict__ bias, float* __restrict__ outp) {
    const int b    = blockIdx.x;
    const int o    = threadIdx.x;
    const int lane = o & 31;
    const int wid  = o >> 5;

    float x = g_s2[b * OO + o] + bias[o];
    g_s0[b * OO + o] = 0.0f;
    g_s1[b * OO + o] = 0.0f;
    g_s2[b * OO + o] = 0.0f;

    float ss = warp_sum(x * x);
    __shared__ float red[32];
    if (lane == 0) red[wid] = ss;
    __syncthreads();
    if (wid == 0) {
        float r = warp_sum(red[lane]);
        if (lane == 0) red[0] = r;
    }
    __syncthreads();

    outp[b * OO + o] = x * squash_f(red[0]);
}

extern "C" void kernel_launch(void* const* d_in, const int* in_sizes, int n_in,
                              void* d_out, int out_size) {
    const float* u    = (const float*)d_in[0];
    const float* w    = (const float*)d_in[1];
    const float* bias = (const float*)d_in[2];
    float* out = (float*)d_out;

    gemv_kernel<<<dim3(16, 8), 256>>>(u, w);
    softmax_kernel<1><<<dim3(NCHUNK, BB / 4), 256>>>(u, w, bias);
    softmax_kernel<2><<<dim3(NCHUNK, BB / 4), 256>>>(u, w, bias);
    final_kernel<<<BB, 1024>>>(bias, out);
}